// round 5
// baseline (speedup 1.0000x reference)
#include <cuda_runtime.h>
#include <cstdint>

// Furthest Point Sampling, exact-match to JAX reference.
// B=16, N=32768, M=2048. One 8-CTA cluster per batch; 4096 pts/CTA in
// f32x2-packed registers. Per iteration: packed update + argmax ->
// redux.sync warp argmax -> smem keys -> worker warp (warp 7) reduces and
// pushes a TAGGED candidate {key(val|inv_idx|tag), xy, z} into every CTA's
// slots via weak cluster stores + one release store of the key. Waiters
// poll their OWN smem slots until all 8 tags match the iteration -> 8-way
// reduce (keys already in regs from the last poll) -> next seed.
// No mbarrier, no cluster arrive, no wakeup latency.

constexpr int NPTS = 32768;
constexpr int MOUT = 2048;
constexpr int CS   = 8;            // cluster size (CTAs per batch)
constexpr int PCTA = NPTS / CS;    // 4096 points per CTA
constexpr int NT   = 256;          // threads per CTA
constexpr int PPT  = PCTA / NT;    // 16 points per thread
constexpr int NPAIR = PPT / 2;     // 8 packed pairs per thread
constexpr int NW   = NT / 32;      // 8 warps

struct __align__(16) ClusterShm {
    unsigned long long warp_keys[NW];
    unsigned long long slot_key[2][CS];   // tagged keys, double-buffered
    unsigned long long slot_xy[2][CS];
    float              slot_z[2][CS];
    float pad_[2 * CS & 1 ? 1 : 2];        // keep 8B alignment (slot_z is 2*8 floats -> ok)
    float sx[PCTA];                        // coordinate copy for winner lookup
    float sy[PCTA];
    float sz[PCTA];
};

__device__ __forceinline__ uint32_t smem_u32(const void* p) {
    return (uint32_t)__cvta_generic_to_shared(p);
}
__device__ __forceinline__ uint32_t mapa_u32(uint32_t a, uint32_t r) {
    uint32_t out;
    asm("mapa.shared::cluster.u32 %0, %1, %2;" : "=r"(out) : "r"(a), "r"(r));
    return out;
}
__device__ __forceinline__ unsigned long long ld_acq_u64(uint32_t a) {
    unsigned long long v;
    asm volatile("ld.acquire.cluster.shared.b64 %0, [%1];" : "=l"(v) : "r"(a) : "memory");
    return v;
}
__device__ __forceinline__ unsigned long long pack2(float lo, float hi) {
    unsigned long long r;
    asm("mov.b64 %0, {%1, %2};" : "=l"(r) : "f"(lo), "f"(hi));
    return r;
}
__device__ __forceinline__ void unpack2(unsigned long long v, float& lo, float& hi) {
    asm("mov.b64 {%0, %1}, %2;" : "=f"(lo), "=f"(hi) : "l"(v));
}
__device__ __forceinline__ unsigned long long addx2(unsigned long long a, unsigned long long b) {
    unsigned long long r;
    asm("add.rn.f32x2 %0, %1, %2;" : "=l"(r) : "l"(a), "l"(b));
    return r;
}
__device__ __forceinline__ unsigned long long mulx2(unsigned long long a, unsigned long long b) {
    unsigned long long r;
    asm("mul.rn.f32x2 %0, %1, %2;" : "=l"(r) : "l"(a), "l"(b));
    return r;
}

__global__ void __launch_bounds__(NT, 1) __cluster_dims__(CS, 1, 1)
fps_kernel(const float* __restrict__ pts, float* __restrict__ out)
{
    extern __shared__ __align__(16) char shm_raw[];
    ClusterShm* s = reinterpret_cast<ClusterShm*>(shm_raw);

    const int tid = threadIdx.x;
    uint32_t rank;
    asm("mov.u32 %0, %%cluster_ctarank;" : "=r"(rank));
    const int batch = blockIdx.x / CS;

    const float* px = pts + (size_t)batch * 3u * NPTS;
    const float* py = px + NPTS;
    const float* pz = px + 2 * NPTS;
    float* ob = out + (size_t)batch * 3u * MOUT;

    // Init tagged slots to an impossible tag (0x7FFF > max j) in both buffers.
    if (tid < 2 * CS) s->slot_key[tid >> 3][tid & 7] = ~0ull;

    // Load this CTA's 4096 points into packed registers (+ smem copy).
    unsigned long long X2[NPAIR], Y2[NPAIR], Z2[NPAIR];
    float d[PPT];
    const int base = (int)rank * PCTA + tid;   // global point index, k-strided
#pragma unroll
    for (int p = 0; p < NPAIR; ++p) {
        const int n0 = base + (2 * p) * NT;        // coalesced
        const int n1 = base + (2 * p + 1) * NT;
        float x0 = px[n0], x1 = px[n1];
        float y0 = py[n0], y1 = py[n1];
        float z0 = pz[n0], z1 = pz[n1];
        X2[p] = pack2(x0, x1);
        Y2[p] = pack2(y0, y1);
        Z2[p] = pack2(z0, z1);
        d[2 * p] = 1e10f; d[2 * p + 1] = 1e10f;
        const int l0 = tid + (2 * p) * NT;
        const int l1 = tid + (2 * p + 1) * NT;
        s->sx[l0] = x0; s->sy[l0] = y0; s->sz[l0] = z0;
        s->sx[l1] = x1; s->sy[l1] = y1; s->sz[l1] = z1;
    }
    // First selected point is global index 0 (CUDA FPS convention).
    float lx = px[0], ly = py[0], lz = pz[0];

    __syncthreads();
    // Slot init visible cluster-wide before any peer can write them.
    asm volatile("barrier.cluster.arrive.aligned;" ::: "memory");
    asm volatile("barrier.cluster.wait.aligned;"   ::: "memory");

    const bool writer = (rank == 0u) && (tid == 0);
    const int lane = tid & 31;
    const int wid  = tid >> 5;

    // Hoisted remote-slot addresses for the worker warp's sending lanes.
    const uint32_t tr = (uint32_t)(lane & 7);            // target CTA rank
    uint32_t a_key[2], a_xy[2], a_z[2];
#pragma unroll
    for (int b = 0; b < 2; ++b) {
        a_key[b] = mapa_u32(smem_u32(&s->slot_key[b][rank]), tr);
        a_xy[b]  = mapa_u32(smem_u32(&s->slot_xy[b][rank]),  tr);
        a_z[b]   = mapa_u32(smem_u32(&s->slot_z[b][rank]),   tr);
    }
    // Local slot-key addresses for polling.
    uint32_t pk[2];
    pk[0] = smem_u32(&s->slot_key[0][0]);
    pk[1] = smem_u32(&s->slot_key[1][0]);

    for (int j = 0; j < MOUT; ++j) {
        // Emit current selection's coordinates (this IS the gathered output).
        if (writer) { ob[j] = lx; ob[MOUT + j] = ly; ob[2 * MOUT + j] = lz; }
        if (j == MOUT - 1) break;

        // --- packed distance update (exact fp32 rn, (dx^2+dy^2)+dz^2) ---
        const unsigned long long nlx2 = pack2(-lx, -lx);
        const unsigned long long nly2 = pack2(-ly, -ly);
        const unsigned long long nlz2 = pack2(-lz, -lz);
#pragma unroll
        for (int p = 0; p < NPAIR; ++p) {
            unsigned long long dx = addx2(X2[p], nlx2);
            unsigned long long dy = addx2(Y2[p], nly2);
            unsigned long long dz = addx2(Z2[p], nlz2);
            unsigned long long dd = addx2(addx2(mulx2(dx, dx), mulx2(dy, dy)),
                                          mulx2(dz, dz));
            float f0, f1; unpack2(dd, f0, f1);
            d[2 * p]     = fminf(d[2 * p],     f0);
            d[2 * p + 1] = fminf(d[2 * p + 1], f1);
        }
        // --- per-thread argmax: pairwise max tree, then first-index scan ---
        float t8[8];
#pragma unroll
        for (int i = 0; i < 8; ++i) t8[i] = fmaxf(d[2 * i], d[2 * i + 1]);
        float t4a = fmaxf(t8[0], t8[1]), t4b = fmaxf(t8[2], t8[3]);
        float t4c = fmaxf(t8[4], t8[5]), t4d = fmaxf(t8[6], t8[7]);
        float bv = fmaxf(fmaxf(t4a, t4b), fmaxf(t4c, t4d));
        int bk = 0;
#pragma unroll
        for (int k = PPT - 1; k >= 0; --k) {   // descending: keeps smallest k
            if (d[k] == bv) bk = k;
        }
        const int bgidx = base + bk * NT;

        // --- warp argmax via redux.sync (dist >= 0: bits order-preserving) ---
        const uint32_t bvbits = __float_as_uint(bv);
        const uint32_t wval = __reduce_max_sync(0xFFFFFFFFu, bvbits);
        const uint32_t cand = (bvbits == wval) ? (uint32_t)bgidx : 0xFFFFFFFFu;
        const uint32_t widx = __reduce_min_sync(0xFFFFFFFFu, cand);
        if (lane == 0) {
            // CTA-internal key: max value wins; tie -> max(~idx) = min idx.
            s->warp_keys[wid] =
                ((unsigned long long)wval << 32) |
                (unsigned long long)(0xFFFFFFFFu - widx);
        }
        __syncthreads();

        const int buf = j & 1;
        const uint32_t tag = (uint32_t)j;     // j <= 2046 < 0x7FFF: unique

        // --- worker warp: CTA argmax + tagged all-to-all push ---
        if (wid == NW - 1) {
            unsigned long long ck = s->warp_keys[0];
#pragma unroll
            for (int w = 1; w < NW; ++w) {
                unsigned long long kk = s->warp_keys[w];
                if (kk > ck) ck = kk;
            }
            const uint32_t g = 0xFFFFFFFFu - (uint32_t)ck;      // global idx
            const int lidx = (int)g - (int)rank * PCTA;          // CTA-local
            const float cx = s->sx[lidx];
            const float cy = s->sy[lidx];
            const float cz = s->sz[lidx];
            const unsigned long long cxy =
                ((unsigned long long)__float_as_uint(cy) << 32) |
                (unsigned long long)__float_as_uint(cx);
            // Tagged exchange key: val(32) | inv_idx(17) | tag(15).
            const unsigned long long tkey =
                ((ck >> 32) << 32) |
                ((unsigned long long)(0x1FFFFu - g) << 15) |
                (unsigned long long)tag;

            // Lanes 0..7: weak coord stores, then RELEASE key store (orders
            // coords before key visibility at the remote CTA).
            asm volatile(
                "{\n\t"
                ".reg .pred p;\n\t"
                "setp.lt.u32 p, %0, 8;\n\t"
                "@p st.shared::cluster.u64 [%1], %4;\n\t"
                "@p st.shared::cluster.u32 [%2], %5;\n\t"
                "@p st.release.cluster.shared::cluster.u64 [%3], %6;\n\t"
                "}"
                :: "r"((uint32_t)lane), "r"(a_xy[buf]), "r"(a_z[buf]),
                   "r"(a_key[buf]),
                   "l"(cxy), "r"(__float_as_uint(cz)), "l"(tkey)
                : "memory");
        }

        // --- all warps: poll own slots until all 8 tags == j ---
        const uint32_t kb = pk[buf];
        unsigned long long kk[CS];
        for (;;) {
#pragma unroll
            for (int c = 0; c < CS; ++c) kk[c] = ld_acq_u64(kb + 8u * c);
            uint32_t bad = 0;
#pragma unroll
            for (int c = 0; c < CS; ++c)
                bad |= ((uint32_t)kk[c] ^ tag) & 0x7FFFu;
            if (!bad) break;
        }
        // --- 8-way reduce (keys already in registers) ---
        unsigned long long gk = kk[0];
        int bs = 0;
#pragma unroll
        for (int c = 1; c < CS; ++c)
            if (kk[c] > gk) { gk = kk[c]; bs = c; }
        const unsigned long long wxy = s->slot_xy[buf][bs];
        lx = __uint_as_float((uint32_t)wxy);
        ly = __uint_as_float((uint32_t)(wxy >> 32));
        lz = s->slot_z[buf][bs];
        // No trailing __syncthreads: slot reuse at j+2 is gated through every
        // peer's j+1 send, which follows its coords-read at j; warp_keys WAR
        // is gated by our own slot tag == j (worker consumed keys first).
    }

    // No CTA exits while peers may still be touching its SMEM.
    asm volatile("barrier.cluster.arrive.aligned;" ::: "memory");
    asm volatile("barrier.cluster.wait.aligned;"   ::: "memory");
}

extern "C" void kernel_launch(void* const* d_in, const int* in_sizes, int n_in,
                              void* d_out, int out_size)
{
    (void)n_in; (void)out_size;
    const float* pts = (const float*)d_in[0];
    float* out = (float*)d_out;
    const int B = in_sizes[0] / (3 * NPTS);   // 16

    const size_t shm = sizeof(ClusterShm);
    cudaFuncSetAttribute(fps_kernel, cudaFuncAttributeMaxDynamicSharedMemorySize,
                         (int)shm);
    fps_kernel<<<B * CS, NT, shm>>>(pts, out);
}

// round 7
// speedup vs baseline: 1.0694x; 1.0694x over previous
#include <cuda_runtime.h>
#include <cstdint>

// Furthest Point Sampling, exact-match to JAX reference.
// B=16, N=32768, M=2048. One 8-CTA cluster per batch; 4096 pts/CTA held in
// f32x2-packed registers across 512 threads (8 pts/thread). Per iteration:
// packed update + mask/ffs argmax -> redux.sync warp argmax -> smem keys ->
// worker warp (highest wid) reduces CTA key and pushes {key,xy,z} to every
// CTA with st.async + mbarrier complete_tx (data+signal in ONE DSMEM trip,
// no release-drain, no separate arrive) -> sleep TRYWAIT on transaction
// barrier -> redundant 8-way reduce -> next seed point.

constexpr int NPTS = 32768;
constexpr int MOUT = 2048;
constexpr int CS   = 8;            // cluster size (CTAs per batch)
constexpr int PCTA = NPTS / CS;    // 4096 points per CTA
constexpr int NT   = 512;          // threads per CTA
constexpr int PPT  = PCTA / NT;    // 8 points per thread
constexpr int NPAIR = PPT / 2;     // 4 packed pairs per thread
constexpr int NW   = NT / 32;      // 16 warps
constexpr unsigned TXB = CS * 20u; // bytes per exchange phase: 8 x (8+8+4)

struct __align__(16) ClusterShm {
    unsigned long long mbar[2];            // transaction barriers, dbl-buffered
    unsigned long long warp_keys[NW];
    unsigned long long slot_key[2][CS];    // candidate slots, dbl-buffered
    unsigned long long slot_xy[2][CS];
    float              slot_z[2][CS];
    float sx[PCTA];                        // coordinate copy for winner lookup
    float sy[PCTA];
    float sz[PCTA];
};

__device__ __forceinline__ uint32_t smem_u32(const void* p) {
    return (uint32_t)__cvta_generic_to_shared(p);
}
__device__ __forceinline__ uint32_t mapa_u32(uint32_t a, uint32_t r) {
    uint32_t out;
    asm("mapa.shared::cluster.u32 %0, %1, %2;" : "=r"(out) : "r"(a), "r"(r));
    return out;
}
// HW-sleep transaction-barrier wait (suspendTime hint -> no hot spin).
__device__ __forceinline__ void mbar_wait_sleep(uint32_t addr, uint32_t parity) {
    asm volatile(
        "{\n\t"
        ".reg .pred P;\n\t"
        "WAITLOOP%=:\n\t"
        "mbarrier.try_wait.parity.acquire.cta.shared::cta.b64 P, [%0], %1, 0x989680;\n\t"
        "@!P bra WAITLOOP%=;\n\t"
        "}"
        :: "r"(addr), "r"(parity) : "memory");
}
__device__ __forceinline__ unsigned long long pack2(float lo, float hi) {
    unsigned long long r;
    asm("mov.b64 %0, {%1, %2};" : "=l"(r) : "f"(lo), "f"(hi));
    return r;
}
__device__ __forceinline__ void unpack2(unsigned long long v, float& lo, float& hi) {
    asm("mov.b64 {%0, %1}, %2;" : "=f"(lo), "=f"(hi) : "l"(v));
}
__device__ __forceinline__ unsigned long long addx2(unsigned long long a, unsigned long long b) {
    unsigned long long r;
    asm("add.rn.f32x2 %0, %1, %2;" : "=l"(r) : "l"(a), "l"(b));
    return r;
}
__device__ __forceinline__ unsigned long long mulx2(unsigned long long a, unsigned long long b) {
    unsigned long long r;
    asm("mul.rn.f32x2 %0, %1, %2;" : "=l"(r) : "l"(a), "l"(b));
    return r;
}

__global__ void __launch_bounds__(NT, 1) __cluster_dims__(CS, 1, 1)
fps_kernel(const float* __restrict__ pts, float* __restrict__ out)
{
    extern __shared__ __align__(16) char shm_raw[];
    ClusterShm* s = reinterpret_cast<ClusterShm*>(shm_raw);

    const int tid = threadIdx.x;
    uint32_t rank;
    asm("mov.u32 %0, %%cluster_ctarank;" : "=r"(rank));
    const int batch = blockIdx.x / CS;

    const float* px = pts + (size_t)batch * 3u * NPTS;
    const float* py = px + NPTS;
    const float* pz = px + 2 * NPTS;
    float* ob = out + (size_t)batch * 3u * MOUT;

    const uint32_t mb0 = smem_u32(&s->mbar[0]);
    const uint32_t mb1 = smem_u32(&s->mbar[1]);
    if (tid == 0) {
        asm volatile("mbarrier.init.shared.b64 [%0], 1;" :: "r"(mb0) : "memory");
        asm volatile("mbarrier.init.shared.b64 [%0], 1;" :: "r"(mb1) : "memory");
        // Arm both buffers for their first phase (arrival + 160 expected bytes).
        asm volatile("mbarrier.arrive.expect_tx.shared.b64 _, [%0], %1;"
                     :: "r"(mb0), "r"(TXB) : "memory");
        asm volatile("mbarrier.arrive.expect_tx.shared.b64 _, [%0], %1;"
                     :: "r"(mb1), "r"(TXB) : "memory");
    }

    // Load this CTA's 4096 points into packed registers (+ smem copy).
    unsigned long long X2[NPAIR], Y2[NPAIR], Z2[NPAIR];
    float d[PPT];
    const int base = (int)rank * PCTA + tid;   // global point index, k-strided
#pragma unroll
    for (int p = 0; p < NPAIR; ++p) {
        const int n0 = base + (2 * p) * NT;        // coalesced
        const int n1 = base + (2 * p + 1) * NT;
        float x0 = px[n0], x1 = px[n1];
        float y0 = py[n0], y1 = py[n1];
        float z0 = pz[n0], z1 = pz[n1];
        X2[p] = pack2(x0, x1);
        Y2[p] = pack2(y0, y1);
        Z2[p] = pack2(z0, z1);
        d[2 * p] = 1e10f; d[2 * p + 1] = 1e10f;
        const int l0 = tid + (2 * p) * NT;
        const int l1 = tid + (2 * p + 1) * NT;
        s->sx[l0] = x0; s->sy[l0] = y0; s->sz[l0] = z0;
        s->sx[l1] = x1; s->sy[l1] = y1; s->sz[l1] = z1;
    }
    // First selected point is global index 0 (CUDA FPS convention).
    float lx = px[0], ly = py[0], lz = pz[0];

    __syncthreads();
    // Barriers armed cluster-wide before any peer st.async can land.
    asm volatile("barrier.cluster.arrive.aligned;" ::: "memory");
    asm volatile("barrier.cluster.wait.aligned;"   ::: "memory");

    const bool writer = (rank == 0u) && (tid == 0);
    const int lane = tid & 31;
    const int wid  = tid >> 5;
    const bool is_worker = (wid == NW - 1);

    // Hoisted remote addresses for the worker warp's 8 sending lanes.
    const uint32_t tr = (uint32_t)(lane & 7);            // target CTA rank
    uint32_t a_key[2], a_xy[2], a_z[2], a_mb[2];
#pragma unroll
    for (int b = 0; b < 2; ++b) {
        a_key[b] = mapa_u32(smem_u32(&s->slot_key[b][rank]), tr);
        a_xy[b]  = mapa_u32(smem_u32(&s->slot_xy[b][rank]),  tr);
        a_z[b]   = mapa_u32(smem_u32(&s->slot_z[b][rank]),   tr);
        a_mb[b]  = mapa_u32(b == 0 ? mb0 : mb1, tr);
    }

    for (int j = 0; j < MOUT; ++j) {
        // Emit current selection's coordinates (this IS the gathered output).
        if (writer) { ob[j] = lx; ob[MOUT + j] = ly; ob[2 * MOUT + j] = lz; }
        if (j == MOUT - 1) break;

        // --- packed distance update (exact fp32 rn, (dx^2+dy^2)+dz^2) ---
        const unsigned long long nlx2 = pack2(-lx, -lx);
        const unsigned long long nly2 = pack2(-ly, -ly);
        const unsigned long long nlz2 = pack2(-lz, -lz);
#pragma unroll
        for (int p = 0; p < NPAIR; ++p) {
            unsigned long long dx = addx2(X2[p], nlx2);
            unsigned long long dy = addx2(Y2[p], nly2);
            unsigned long long dz = addx2(Z2[p], nlz2);
            unsigned long long dd = addx2(addx2(mulx2(dx, dx), mulx2(dy, dy)),
                                          mulx2(dz, dz));
            float f0, f1; unpack2(dd, f0, f1);
            d[2 * p]     = fminf(d[2 * p],     f0);
            d[2 * p + 1] = fminf(d[2 * p + 1], f1);
        }
        // --- per-thread argmax: shallow max tree + parallel mask + ffs ---
        float t4a = fmaxf(d[0], d[1]), t4b = fmaxf(d[2], d[3]);
        float t4c = fmaxf(d[4], d[5]), t4d = fmaxf(d[6], d[7]);
        const float bv = fmaxf(fmaxf(t4a, t4b), fmaxf(t4c, t4d));
        uint32_t mask = 0;
#pragma unroll
        for (int k = 0; k < PPT; ++k) mask |= (d[k] == bv) ? (1u << k) : 0u;
        const int bk = __ffs(mask) - 1;      // smallest k -> smallest gidx
        const int bgidx = base + bk * NT;

        // --- warp argmax via redux.sync (dist >= 0: bits order-preserving) ---
        const uint32_t bvbits = __float_as_uint(bv);
        const uint32_t wval = __reduce_max_sync(0xFFFFFFFFu, bvbits);
        const uint32_t cand = (bvbits == wval) ? (uint32_t)bgidx : 0xFFFFFFFFu;
        const uint32_t widx = __reduce_min_sync(0xFFFFFFFFu, cand);
        if (lane == 0) {
            // key: max value wins; tie -> max(~idx) = min idx (first occurrence)
            s->warp_keys[wid] =
                ((unsigned long long)wval << 32) |
                (unsigned long long)(0xFFFFFFFFu - widx);
        }
        __syncthreads();

        const int buf = j & 1;
        const uint32_t parity = (uint32_t)(j >> 1) & 1u;

        // --- worker warp: CTA argmax + fused data+signal all-to-all push ---
        if (is_worker) {
            unsigned long long ck = s->warp_keys[0];   // broadcast LDS
#pragma unroll
            for (int w = 1; w < NW; ++w) {
                unsigned long long kk = s->warp_keys[w];
                if (kk > ck) ck = kk;
            }
            const uint32_t g = 0xFFFFFFFFu - (uint32_t)ck;      // global idx
            const int lidx = (int)g - (int)rank * PCTA;          // CTA-local
            const float cx = s->sx[lidx];
            const float cy = s->sy[lidx];
            const float cz = s->sz[lidx];
            const unsigned long long cxy =
                ((unsigned long long)__float_as_uint(cy) << 32) |
                (unsigned long long)__float_as_uint(cx);

            // Lanes 0..7: three st.async stores, each carrying complete_tx
            // to the TARGET CTA's transaction barrier. One DSMEM trip total.
            asm volatile(
                "{\n\t"
                ".reg .pred p;\n\t"
                "setp.lt.u32 p, %0, 8;\n\t"
                "@p st.async.shared::cluster.mbarrier::complete_tx::bytes.b64 [%1], %4, [%7];\n\t"
                "@p st.async.shared::cluster.mbarrier::complete_tx::bytes.b64 [%2], %5, [%7];\n\t"
                "@p st.async.shared::cluster.mbarrier::complete_tx::bytes.b32 [%3], %6, [%7];\n\t"
                "}"
                :: "r"((uint32_t)lane), "r"(a_key[buf]), "r"(a_xy[buf]),
                   "r"(a_z[buf]),
                   "l"(ck), "l"(cxy), "r"(__float_as_uint(cz)), "r"(a_mb[buf])
                : "memory");
        }

        // --- sleep-wait for all 160 bytes (8 CTAs x 20B) ---
        mbar_wait_sleep(buf ? mb1 : mb0, parity);

        // Re-arm this buffer for its next phase (j+2). Safe: peers can only
        // send j+2 after observing our j+1 message, which we send after this
        // point; and negative-tx counting makes even late arms correct.
        if (is_worker && lane == 0) {
            asm volatile("mbarrier.arrive.expect_tx.shared.b64 _, [%0], %1;"
                         :: "r"(buf ? mb1 : mb0), "r"(TXB) : "memory");
        }

        // --- redundant 8-way reduce (per warp, broadcast LDS) ---
        unsigned long long gk = s->slot_key[buf][0];
        int bs = 0;
#pragma unroll
        for (int c = 1; c < CS; ++c) {
            unsigned long long kk = s->slot_key[buf][c];
            if (kk > gk) { gk = kk; bs = c; }
        }
        const unsigned long long wxy = s->slot_xy[buf][bs];
        lx = __uint_as_float((uint32_t)wxy);
        ly = __uint_as_float((uint32_t)(wxy >> 32));
        lz = s->slot_z[buf][bs];
        // No trailing __syncthreads: slot/barrier reuse at j+2 is gated
        // through every peer's j+1 send (which follows its j consumption);
        // warp_keys WAR is gated by our own barrier completing phase j.
    }

    // No CTA exits while peers may still be touching its SMEM.
    asm volatile("barrier.cluster.arrive.aligned;" ::: "memory");
    asm volatile("barrier.cluster.wait.aligned;"   ::: "memory");
}

extern "C" void kernel_launch(void* const* d_in, const int* in_sizes, int n_in,
                              void* d_out, int out_size)
{
    (void)n_in; (void)out_size;
    const float* pts = (const float*)d_in[0];
    float* out = (float*)d_out;
    const int B = in_sizes[0] / (3 * NPTS);   // 16

    const size_t shm = sizeof(ClusterShm);
    cudaFuncSetAttribute(fps_kernel, cudaFuncAttributeMaxDynamicSharedMemorySize,
                         (int)shm);
    fps_kernel<<<B * CS, NT, shm>>>(pts, out);
}